// round 1
// baseline (speedup 1.0000x reference)
#include <cuda_runtime.h>

// Problem constants (upper bounds; actual N,E taken from in_sizes)
#define MAXN 40000
#define FDIM 128

// Scratch (static __device__ — no allocation allowed)
__device__ float g_agg[MAXN * FDIM];
__device__ float g_h1 [MAXN * FDIM];
__device__ float g_h2 [MAXN * FDIM];
__device__ float g_stats [2 * MAXN];  // [0,N): deg   [N,2N): sum_w
__device__ float g_scales[2 * MAXN];  // [0,N): sm    [N,2N): sh

// ---------------------------------------------------------------------------
__global__ void zero_stats_kernel(int n) {
    int i = blockIdx.x * blockDim.x + threadIdx.x;
    if (i < 2 * n) g_stats[i] = 0.0f;
}

__global__ void zero_agg_kernel(int n_float4) {
    float4* p = reinterpret_cast<float4*>(g_agg);
    for (int i = blockIdx.x * blockDim.x + threadIdx.x; i < n_float4;
         i += gridDim.x * blockDim.x)
        p[i] = make_float4(0.f, 0.f, 0.f, 0.f);
}

// deg[d] += 1, sumw[d] += w  (RED, no return)
__global__ void edge_stats_kernel(const int* __restrict__ dst,
                                  const float* __restrict__ w,
                                  int E, int n) {
    int e = blockIdx.x * blockDim.x + threadIdx.x;
    if (e >= E) return;
    int d = dst[e];
    atomicAdd(&g_stats[d], 1.0f);
    atomicAdd(&g_stats[n + d], w[e]);
}

// sm = deg/((deg+1)*sum_w'), sh = 1/(deg+1); both 0 when deg==0
__global__ void scales_kernel(int n) {
    int i = blockIdx.x * blockDim.x + threadIdx.x;
    if (i >= n) return;
    float dg = g_stats[i];
    float sw = g_stats[n + i];
    float smv = 0.f, shv = 0.f;
    if (dg > 0.f) {
        float inv = 1.0f / (dg + 1.0f);
        shv = inv;
        float swp = (sw == 0.f) ? 1.f : sw;
        smv = dg * inv / swp;
    }
    g_scales[i]     = smv;
    g_scales[n + i] = shv;
}

// Warp-per-edge weighted gather-scatter: agg[dst] += h[src] * w
// Each lane handles one float4 (128 floats = 32 lanes * float4).
__global__ void __launch_bounds__(256)
agg_kernel(const float4* __restrict__ h,
           const int* __restrict__ src, const int* __restrict__ dst,
           const float* __restrict__ w, int E) {
    int gw   = (blockIdx.x * blockDim.x + threadIdx.x) >> 5;
    int lane = threadIdx.x & 31;
    if (gw >= E) return;
    int s = src[gw];
    int d = dst[gw];
    float wt = w[gw];
    float4 v = h[s * 32 + lane];
    v.x *= wt; v.y *= wt; v.z *= wt; v.w *= wt;
    float* addr = &g_agg[d * FDIM + lane * 4];
    asm volatile("red.global.add.v4.f32 [%0], {%1,%2,%3,%4};"
                 :: "l"(addr), "f"(v.x), "f"(v.y), "f"(v.z), "f"(v.w)
                 : "memory");
}

// Fused: X = sm*agg + sh*hin ; hout = relu(X @ W^T + b)
// Tile: 32 nodes x 128 outs per block iteration.
// SMEM: W transposed [k][o] pitch 132 (conflict-free float4 reads),
//       X tile [32][128].
#define WPITCH 132
__global__ void __launch_bounds__(256)
update_kernel(const float* __restrict__ hin,
              const float* __restrict__ W,     // [128,128] row-major [o][k]
              const float* __restrict__ bias,  // [128]
              float* __restrict__ hout,        // [N,128]
              int n) {
    extern __shared__ float smem[];
    float* Ws = smem;                 // 128 * 132
    float* Xs = smem + FDIM * WPITCH; // 32 * 128
    int tid = threadIdx.x;

    for (int i = tid; i < FDIM * FDIM; i += 256) {
        int o = i >> 7, k = i & 127;
        Ws[k * WPITCH + o] = W[i];
    }

    int lane = tid & 31;
    int wp   = tid >> 5;
    float4 bv = *reinterpret_cast<const float4*>(&bias[lane * 4]);

    int ntiles = n >> 5;
    for (int tile = blockIdx.x; tile < ntiles; tile += gridDim.x) {
        __syncthreads();  // Ws visible / previous tile's compute done
        int n0 = tile << 5;
        for (int i = tid; i < 32 * FDIM; i += 256) {
            int node = n0 + (i >> 7);
            int k = i & 127;
            Xs[i] = g_scales[node] * g_agg[node * FDIM + k]
                  + g_scales[n + node] * hin[node * FDIM + k];
        }
        __syncthreads();

        float acc[4][4];
#pragma unroll
        for (int j = 0; j < 4; j++) {
            acc[j][0] = bv.x; acc[j][1] = bv.y;
            acc[j][2] = bv.z; acc[j][3] = bv.w;
        }
#pragma unroll 4
        for (int k = 0; k < FDIM; k++) {
            float4 wv = *reinterpret_cast<const float4*>(&Ws[k * WPITCH + lane * 4]);
#pragma unroll
            for (int j = 0; j < 4; j++) {
                float xv = Xs[((wp << 2) + j) * FDIM + k];
                acc[j][0] += xv * wv.x;
                acc[j][1] += xv * wv.y;
                acc[j][2] += xv * wv.z;
                acc[j][3] += xv * wv.w;
            }
        }
#pragma unroll
        for (int j = 0; j < 4; j++) {
            int node = n0 + (wp << 2) + j;
            float4 r;
            r.x = fmaxf(acc[j][0], 0.f);
            r.y = fmaxf(acc[j][1], 0.f);
            r.z = fmaxf(acc[j][2], 0.f);
            r.w = fmaxf(acc[j][3], 0.f);
            *reinterpret_cast<float4*>(&hout[node * FDIM + lane * 4]) = r;
        }
    }
}

// Final classifier: out = h2 @ Wo^T + bo   ([N,128] x [32,128]^T -> [N,32])
// Warp per node, lane = output channel, x broadcast via shfl.
__global__ void __launch_bounds__(256)
out_kernel(const float4* __restrict__ h2,
           const float* __restrict__ Wo,   // [32,128] row-major [o][k]
           const float* __restrict__ bo,   // [32]
           float* __restrict__ out, int n) {
    __shared__ float Wos[FDIM * 32];  // [k][o]
    int tid = threadIdx.x;
    for (int i = tid; i < 32 * FDIM; i += 256) {
        int o = i >> 7, k = i & 127;
        Wos[k * 32 + o] = Wo[i];
    }
    __syncthreads();

    int lane = tid & 31;
    int wp   = tid >> 5;
    float bias = bo[lane];
    for (int node = blockIdx.x * 8 + wp; node < n; node += gridDim.x * 8) {
        float4 x = h2[node * 32 + lane];  // lane-th float4 of the row
        float acc = bias;
#pragma unroll
        for (int j = 0; j < 32; j++) {
            float a = __shfl_sync(0xffffffffu, x.x, j);
            float b = __shfl_sync(0xffffffffu, x.y, j);
            float c = __shfl_sync(0xffffffffu, x.z, j);
            float d = __shfl_sync(0xffffffffu, x.w, j);
            int k = j << 2;
            acc += a * Wos[(k + 0) * 32 + lane];
            acc += b * Wos[(k + 1) * 32 + lane];
            acc += c * Wos[(k + 2) * 32 + lane];
            acc += d * Wos[(k + 3) * 32 + lane];
        }
        out[node * 32 + lane] = acc;
    }
}

// ---------------------------------------------------------------------------
extern "C" void kernel_launch(void* const* d_in, const int* in_sizes, int n_in,
                              void* d_out, int out_size) {
    const float* features = (const float*)d_in[0];
    const int*   src      = (const int*)  d_in[1];
    const int*   dst      = (const int*)  d_in[2];
    const float* weight   = (const float*)d_in[3];
    const float* W1       = (const float*)d_in[4];
    const float* b1       = (const float*)d_in[5];
    const float* W2       = (const float*)d_in[6];
    const float* b2       = (const float*)d_in[7];
    const float* Wo       = (const float*)d_in[8];
    const float* bo       = (const float*)d_in[9];
    float* out = (float*)d_out;

    int N = in_sizes[0] / FDIM;
    int E = in_sizes[1];

    void *ph1_v, *ph2_v;
    cudaGetSymbolAddress(&ph1_v, g_h1);
    cudaGetSymbolAddress(&ph2_v, g_h2);
    float* ph1 = (float*)ph1_v;
    float* ph2 = (float*)ph2_v;

    const int smem_bytes = (FDIM * WPITCH + 32 * FDIM) * (int)sizeof(float); // 83968
    cudaFuncSetAttribute(update_kernel,
                         cudaFuncAttributeMaxDynamicSharedMemorySize, smem_bytes);

    // Edge stats (shared by both layers)
    zero_stats_kernel<<<(2 * N + 255) / 256, 256>>>(N);
    edge_stats_kernel<<<(E + 255) / 256, 256>>>(dst, weight, E, N);
    scales_kernel<<<(N + 255) / 256, 256>>>(N);

    // Layer 1
    zero_agg_kernel<<<1024, 256>>>(N * (FDIM / 4));
    agg_kernel<<<(E + 7) / 8, 256>>>((const float4*)features, src, dst, weight, E);
    update_kernel<<<304, 256, smem_bytes>>>(features, W1, b1, ph1, N);

    // Layer 2
    zero_agg_kernel<<<1024, 256>>>(N * (FDIM / 4));
    agg_kernel<<<(E + 7) / 8, 256>>>((const float4*)ph1, src, dst, weight, E);
    update_kernel<<<304, 256, smem_bytes>>>(ph1, W2, b2, ph2, N);

    // Classifier
    out_kernel<<<2048, 256>>>((const float4*)ph2, Wo, bo, out, N);
}